// round 12
// baseline (speedup 1.0000x reference)
#include <cuda_runtime.h>
#include <cuda_fp16.h>
#include <cstdint>
#include <math.h>

#define TT 8192
#define NE 8
#define HD 2048
#define ID 5632
#define NROW (TT*2)

// ---------------- scratch (static device globals) ----------------
__device__ int    g_count[NE];
__device__ int    g_base[NE];
__device__ int    g_ctr[NE];
__device__ int    g_blkbase[NE + 1];
__device__ int    g_tok_e[TT*2];
__device__ float  g_tok_w[TT*2];
__device__ int    g_row_of[TT*2];
__device__ int    g_tok_of_row[NROW];
__device__ float  g_w_of_row[NROW];
__device__ __half g_xh [(size_t)TT*HD];
__device__ __half g_w2h[(size_t)NE*HD*ID];
__device__ __half g_act[(size_t)NROW*ID];

// ---------------- helpers ----------------
__device__ __forceinline__ void cpa16(uint32_t dst, uint64_t gsrc) {
    asm volatile("cp.async.cg.shared.global [%0], [%1], 16;" :: "r"(dst), "l"(gsrc));
}
#define CPA_COMMIT() asm volatile("cp.async.commit_group;" ::: "memory")
#define CPA_WAIT(n)  asm volatile("cp.async.wait_group %0;" :: "n"(n) : "memory")

__device__ __forceinline__ uint32_t smem_u32(const void* p) {
    uint32_t a;
    asm("{ .reg .u64 t; cvta.to.shared.u64 t, %1; cvt.u32.u64 %0, t; }" : "=r"(a) : "l"(p));
    return a;
}

__device__ __forceinline__ void mma_f16(float* c, const uint32_t* a, const uint32_t* b) {
    asm volatile(
        "mma.sync.aligned.m16n8k16.row.col.f32.f16.f16.f32 "
        "{%0,%1,%2,%3},{%4,%5,%6,%7},{%8,%9},{%0,%1,%2,%3};"
        : "+f"(c[0]), "+f"(c[1]), "+f"(c[2]), "+f"(c[3])
        : "r"(a[0]), "r"(a[1]), "r"(a[2]), "r"(a[3]), "r"(b[0]), "r"(b[1]));
}

__device__ __forceinline__ uint32_t f2h2(float lo, float hi) {
    __half2 h = __floats2half2_rn(lo, hi);
    return *reinterpret_cast<uint32_t*>(&h);
}

// ---------------- routing ----------------
__global__ void zero_meta_kernel() { if (threadIdx.x < NE) g_count[threadIdx.x] = 0; }

__global__ void route_count_kernel(const float* __restrict__ logits) {
    int t = blockIdx.x * blockDim.x + threadIdx.x;
    if (t >= TT) return;
    float v[NE];
#pragma unroll
    for (int e = 0; e < NE; e++) v[e] = logits[t * NE + e];
    int i0 = 0; float m0 = v[0];
#pragma unroll
    for (int e = 1; e < NE; e++) if (v[e] > m0) { m0 = v[e]; i0 = e; }
    int i1 = -1; float m1 = -INFINITY;
#pragma unroll
    for (int e = 0; e < NE; e++) if (e != i0 && v[e] > m1) { m1 = v[e]; i1 = e; }
    float z = expf(m1 - m0);
    float w0 = 1.0f / (1.0f + z);
    g_tok_e[t*2+0] = i0; g_tok_e[t*2+1] = i1;
    g_tok_w[t*2+0] = w0; g_tok_w[t*2+1] = z * w0;
    atomicAdd(&g_count[i0], 1);
    atomicAdd(&g_count[i1], 1);
}

__global__ void scan_kernel() {
    int acc = 0, pb = 0;
    for (int e = 0; e < NE; e++) {
        g_base[e] = acc; acc += g_count[e]; g_ctr[e] = 0;
        g_blkbase[e] = pb; pb += (g_count[e] + 127) >> 7;
    }
    g_blkbase[NE] = pb;
}

__global__ void route_scatter_kernel() {
    int t = blockIdx.x * blockDim.x + threadIdx.x;
    if (t >= TT) return;
#pragma unroll
    for (int k = 0; k < 2; k++) {
        int e = g_tok_e[t*2+k];
        int slot = atomicAdd(&g_ctr[e], 1);
        int row = g_base[e] + slot;
        g_row_of[t*2+k] = row;
        g_tok_of_row[row] = t;
        g_w_of_row[row] = g_tok_w[t*2+k];
    }
}

// ---------------- fp32 -> fp16 convert (2 float4 per thread) ----------------
__global__ void to_half_kernel(const float4* __restrict__ in, uint2* __restrict__ out, int n4) {
    int i = (blockIdx.x * blockDim.x + threadIdx.x) * 2;
#pragma unroll
    for (int q = 0; q < 2; q++) {
        int j = i + q;
        if (j >= n4) return;
        float4 v = in[j];
        __half2 h0 = __floats2half2_rn(v.x, v.y);
        __half2 h1 = __floats2half2_rn(v.z, v.w);
        uint2 o;
        o.x = *reinterpret_cast<uint32_t*>(&h0);
        o.y = *reinterpret_cast<uint32_t*>(&h1);
        out[j] = o;
    }
}

// ---------------- GEMM config ----------------
#define BKH  32
#define PFH  40                            // A row stride in halves (20 words)
#define PFW  40                            // B row stride in fp32 words (GEMM1)
#define A_TILE (128*PFH*2)                 // 10240 B (fp16 A stage)
#define B_TILE32 (128*PFW*4)               // 20480 B (fp32 B stage, GEMM1)
#define NSTG1 3
#define STG1_B (A_TILE + B_TILE32)         // 30720 per stage
#define GEMM1_SMEM (NSTG1*STG1_B)          // 92160

#define TILE_H (128*PFH)
#define STG_B  (TILE_H*2)                  // 10240 (fp16 tile, GEMM2)
#define NSTG 4
#define GEMM2_SMEM (2*NSTG*STG_B)          // 81920
#define GRID_X (NROW/128 + NE)

// GEMM1: A = gathered x (fp16), B = raw fp32 w1/w3 rows, in-register cvt.
// B rows 0..63 = w1 (gate), 64..127 = w3 (up), same 64 I-cols.
__global__ void __launch_bounds__(256, 2) gemm1_mma_kernel(
    const float* __restrict__ w1f, const float* __restrict__ w3f)
{
    extern __shared__ char sm[];

    const int bx = blockIdx.x;
    if (bx >= g_blkbase[NE]) return;
    int e = 0;
#pragma unroll
    for (int k = 1; k < NE; k++) if (bx >= g_blkbase[k]) e = k;
    const int row0 = (bx - g_blkbase[e]) * 128;
    const int cnt = g_count[e];
    const int base = g_base[e];
    const int nI = blockIdx.y * 64;

    const int tid  = threadIdx.x;
    const int warp = tid >> 5;
    const int lane = tid & 31;
    const int wm = warp & 1;
    const int wn = warp >> 1;
    const int g  = lane >> 2;
    const int tg = lane & 3;

    const int lrow = tid >> 1;                 // 0..127
    const int lc16 = (tid & 1) * 16;           // 16-element offset (halves for A, floats for B)

    int gr = row0 + lrow;
    int tok = (gr < cnt) ? g_tok_of_row[base + gr] : 0;
    const uint64_t aG = (uint64_t)__cvta_generic_to_global(g_xh + (size_t)tok * HD + lc16);
    const float* bptr = (lrow < 64)
        ? w1f + ((size_t)e * ID + nI + lrow) * HD + lc16
        : w3f + ((size_t)e * ID + nI + (lrow - 64)) * HD + lc16;
    const uint64_t bG = (uint64_t)__cvta_generic_to_global(bptr);

    const uint32_t smB = smem_u32(sm);
    const uint32_t aS = smB + (uint32_t)(lrow * PFH + lc16) * 2;
    const uint32_t bS = smB + A_TILE * NSTG1 + (uint32_t)(lrow * PFW + lc16) * 4;

    float acc[4][4][4];
#pragma unroll
    for (int i = 0; i < 4; i++)
#pragma unroll
        for (int j = 0; j < 4; j++)
#pragma unroll
            for (int q = 0; q < 4; q++) acc[i][j][q] = 0.f;

    const int NS = HD / BKH;  // 64
    // prologue: 2 stages. A: 32 halves/row (each thread 16 halves = 32B -> 2 cpa16)
    //                     B: 32 floats/row (each thread 16 floats = 64B -> 4 cpa16)
#pragma unroll
    for (int p = 0; p < NSTG1 - 1; p++) {
        uint32_t aso = p * A_TILE;
        uint32_t bso = p * B_TILE32;
        uint64_t ka = (uint64_t)p * BKH * 2;
        uint64_t kb = (uint64_t)p * BKH * 4;
        cpa16(aS + aso, aG + ka); cpa16(aS + aso + 16, aG + ka + 16);
        cpa16(bS + bso, bG + kb); cpa16(bS + bso + 16, bG + kb + 16);
        cpa16(bS + bso + 32, bG + kb + 32); cpa16(bS + bso + 48, bG + kb + 48);
        CPA_COMMIT();
    }

    int buf = 0, pbuf = NSTG1 - 1;
    for (int s = 0; s < NS; s++) {
        CPA_WAIT(1);
        __syncthreads();
        if (s + NSTG1 - 1 < NS) {
            uint32_t aso = pbuf * A_TILE;
            uint32_t bso = pbuf * B_TILE32;
            uint64_t ka = (uint64_t)(s + NSTG1 - 1) * BKH * 2;
            uint64_t kb = (uint64_t)(s + NSTG1 - 1) * BKH * 4;
            cpa16(aS + aso, aG + ka); cpa16(aS + aso + 16, aG + ka + 16);
            cpa16(bS + bso, bG + kb); cpa16(bS + bso + 16, bG + kb + 16);
            cpa16(bS + bso + 32, bG + kb + 32); cpa16(bS + bso + 48, bG + kb + 48);
        }
        CPA_COMMIT();

        const uint32_t* A = (const uint32_t*)(sm + buf * A_TILE);
        const float*    B = (const float*)(sm + A_TILE * NSTG1 + buf * B_TILE32);
#pragma unroll
        for (int kc = 0; kc < 2; kc++) {
            uint32_t a[4][4], b[4][2];
            const int kb = kc * 8;     // word offset (A)
            const int kbf = kc * 16;   // float offset (B)
#pragma unroll
            for (int mf = 0; mf < 4; mf++) {
                int mb = wm * 64 + mf * 16 + g;
                a[mf][0] = A[mb * 20 + kb + tg];
                a[mf][1] = A[(mb + 8) * 20 + kb + tg];
                a[mf][2] = A[mb * 20 + kb + tg + 4];
                a[mf][3] = A[(mb + 8) * 20 + kb + tg + 4];
            }
#pragma unroll
            for (int nf = 0; nf < 4; nf++) {
                int nb = wn * 32 + nf * 8 + g;
                float2 f0 = *(const float2*)(B + nb * PFW + kbf + 2 * tg);
                float2 f1 = *(const float2*)(B + nb * PFW + kbf + 2 * tg + 8);
                b[nf][0] = f2h2(f0.x, f0.y);
                b[nf][1] = f2h2(f1.x, f1.y);
            }
#pragma unroll
            for (int mf = 0; mf < 4; mf++)
#pragma unroll
                for (int nf = 0; nf < 4; nf++) mma_f16(acc[mf][nf], a[mf], b[nf]);
        }
        buf = (buf == NSTG1 - 1) ? 0 : buf + 1;
        pbuf = (pbuf == NSTG1 - 1) ? 0 : pbuf + 1;
    }
    __syncthreads();

    // epilogue: up warps (wn>=2) stage accums via smem; gate warps apply silu*up
    float* up_s = (float*)sm;  // 128 x 64, stride 65 = 33280B (fits in 92KB)
    if (wn >= 2) {
#pragma unroll
        for (int mf = 0; mf < 4; mf++) {
#pragma unroll
            for (int nf = 0; nf < 4; nf++) {
                int r = wm * 64 + mf * 16 + g;
                int c = (wn - 2) * 32 + nf * 8 + 2 * tg;
                up_s[r * 65 + c]           = acc[mf][nf][0];
                up_s[r * 65 + c + 1]       = acc[mf][nf][1];
                up_s[(r + 8) * 65 + c]     = acc[mf][nf][2];
                up_s[(r + 8) * 65 + c + 1] = acc[mf][nf][3];
            }
        }
    }
    __syncthreads();
    if (wn < 2) {
#pragma unroll
        for (int mf = 0; mf < 4; mf++) {
#pragma unroll
            for (int nf = 0; nf < 4; nf++) {
                int r = wm * 64 + mf * 16 + g;
                int c = wn * 32 + nf * 8 + 2 * tg;
#pragma unroll
                for (int half = 0; half < 2; half++) {
                    int rr = r + half * 8;
                    int grow = row0 + rr;
                    if (grow >= cnt) continue;
                    float gv0 = acc[mf][nf][half * 2 + 0];
                    float gv1 = acc[mf][nf][half * 2 + 1];
                    float u0 = up_s[rr * 65 + c];
                    float u1 = up_s[rr * 65 + c + 1];
                    float s0 = gv0 / (1.0f + __expf(-gv0));
                    float s1 = gv1 / (1.0f + __expf(-gv1));
                    __half2 h = __floats2half2_rn(s0 * u0, s1 * u1);
                    *(__half2*)(g_act + (size_t)(base + grow) * ID + nI + c) = h;
                }
            }
        }
    }
}

// GEMM2: out[tok] += w_row * (act @ w2^T) — combine fused via atomicAdd (R10 core).
__global__ void __launch_bounds__(256, 2) gemm2_mma_kernel(float* __restrict__ out) {
    extern __shared__ char sm[];
    char* AsB = sm;
    char* BsB = sm + NSTG * STG_B;

    const int bx = blockIdx.x;
    if (bx >= g_blkbase[NE]) return;
    int e = 0;
#pragma unroll
    for (int k = 1; k < NE; k++) if (bx >= g_blkbase[k]) e = k;
    const int row0 = (bx - g_blkbase[e]) * 128;
    const int cnt = g_count[e];
    const int base = g_base[e];
    const int n0b = blockIdx.y * 128;

    const int tid  = threadIdx.x;
    const int warp = tid >> 5;
    const int lane = tid & 31;
    const int wm = warp & 1;
    const int wn = warp >> 1;
    const int g  = lane >> 2;
    const int tg = lane & 3;

    const int lrow = tid >> 1;
    const int lcol = (tid & 1) * 16;

    int gr = row0 + lrow; if (gr >= cnt) gr = cnt - 1;
    const uint64_t aG = (uint64_t)__cvta_generic_to_global(g_act + (size_t)(base + gr) * ID + lcol);
    const uint64_t bG = (uint64_t)__cvta_generic_to_global(g_w2h + ((size_t)e * HD + n0b + lrow) * ID + lcol);

    const uint32_t aS = smem_u32(AsB) + (uint32_t)(lrow * PFH + lcol) * 2;
    const uint32_t bS = smem_u32(BsB) + (uint32_t)(lrow * PFH + lcol) * 2;

    float acc[4][4][4];
#pragma unroll
    for (int i = 0; i < 4; i++)
#pragma unroll
        for (int j = 0; j < 4; j++)
#pragma unroll
            for (int q = 0; q < 4; q++) acc[i][j][q] = 0.f;

    const int NS = ID / BKH;  // 176
#pragma unroll
    for (int p = 0; p < NSTG - 1; p++) {
        uint32_t so = p * STG_B;
        uint64_t ko = (uint64_t)p * BKH * 2;
        cpa16(aS + so, aG + ko); cpa16(aS + so + 16, aG + ko + 16);
        cpa16(bS + so, bG + ko); cpa16(bS + so + 16, bG + ko + 16);
        CPA_COMMIT();
    }

    for (int s = 0; s < NS; s++) {
        CPA_WAIT(NSTG - 2);
        __syncthreads();
        if (s + NSTG - 1 < NS) {
            uint32_t so = ((s + NSTG - 1) & (NSTG - 1)) * STG_B;
            uint64_t ko = (uint64_t)(s + NSTG - 1) * BKH * 2;
            cpa16(aS + so, aG + ko); cpa16(aS + so + 16, aG + ko + 16);
            cpa16(bS + so, bG + ko); cpa16(bS + so + 16, bG + ko + 16);
        }
        CPA_COMMIT();

        const uint32_t* A = (const uint32_t*)(AsB + (s & (NSTG - 1)) * STG_B);
        const uint32_t* B = (const uint32_t*)(BsB + (s & (NSTG - 1)) * STG_B);
#pragma unroll
        for (int kc = 0; kc < 2; kc++) {
            uint32_t a[4][4], b[4][2];
            const int kb = kc * 8;
#pragma unroll
            for (int mf = 0; mf < 4; mf++) {
                int mb = wm * 64 + mf * 16 + g;
                a[mf][0] = A[mb * 20 + kb + tg];
                a[mf][1] = A[(mb + 8) * 20 + kb + tg];
                a[mf][2] = A[mb * 20 + kb + tg + 4];
                a[mf][3] = A[(mb + 8) * 20 + kb + tg + 4];
            }
#pragma unroll
            for (int nf = 0; nf < 4; nf++) {
                int nb = wn * 32 + nf * 8 + g;
                b[nf][0] = B[nb * 20 + kb + tg];
                b[nf][1] = B[nb * 20 + kb + tg + 4];
            }
#pragma unroll
            for (int mf = 0; mf < 4; mf++)
#pragma unroll
                for (int nf = 0; nf < 4; nf++) mma_f16(acc[mf][nf], a[mf], b[nf]);
        }
    }

#pragma unroll
    for (int mf = 0; mf < 4; mf++) {
#pragma unroll
        for (int nf = 0; nf < 4; nf++) {
            int r = wm * 64 + mf * 16 + g;
            int c = wn * 32 + nf * 8 + 2 * tg;
#pragma unroll
            for (int half = 0; half < 2; half++) {
                int rr = r + half * 8;
                int grow = row0 + rr;
                if (grow >= cnt) continue;
                int tok2 = g_tok_of_row[base + grow];
                float wr = g_w_of_row[base + grow];
                float* op = out + (size_t)tok2 * HD + n0b + c;
                atomicAdd(op,     wr * acc[mf][nf][half * 2 + 0]);
                atomicAdd(op + 1, wr * acc[mf][nf][half * 2 + 1]);
            }
        }
    }
}

// ---------------- launch ----------------
extern "C" void kernel_launch(void* const* d_in, const int* in_sizes, int n_in,
                              void* d_out, int out_size)
{
    const float* hidden = (const float*)d_in[0];
    const float* logits = (const float*)d_in[1];
    const float* w1 = (const float*)d_in[2];
    const float* w2 = (const float*)d_in[3];
    const float* w3 = (const float*)d_in[4];
    float* out = (float*)d_out;

    static int init_done = 0;
    static cudaStream_t sA, sB;
    static cudaEvent_t evRoot, evA, evB;
    if (!init_done) {
        cudaFuncSetAttribute(gemm1_mma_kernel, cudaFuncAttributeMaxDynamicSharedMemorySize, GEMM1_SMEM);
        cudaFuncSetAttribute(gemm2_mma_kernel, cudaFuncAttributeMaxDynamicSharedMemorySize, GEMM2_SMEM);
        cudaStreamCreateWithFlags(&sA, cudaStreamNonBlocking);
        cudaStreamCreateWithFlags(&sB, cudaStreamNonBlocking);
        cudaEventCreateWithFlags(&evRoot, cudaEventDisableTiming);
        cudaEventCreateWithFlags(&evA, cudaEventDisableTiming);
        cudaEventCreateWithFlags(&evB, cudaEventDisableTiming);
        init_done = 1;
    }

    __half *xh_p, *w2_p;
    cudaGetSymbolAddress((void**)&xh_p, g_xh);
    cudaGetSymbolAddress((void**)&w2_p, g_w2h);

    // fork
    cudaEventRecord(evRoot, 0);
    cudaStreamWaitEvent(sA, evRoot, 0);
    cudaStreamWaitEvent(sB, evRoot, 0);

    // branch A: routing chain — hidden under x convert + GEMM1 start
    zero_meta_kernel<<<1, 32, 0, sA>>>();
    route_count_kernel<<<(TT + 255) / 256, 256, 0, sA>>>(logits);
    scan_kernel<<<1, 1, 0, sA>>>();
    route_scatter_kernel<<<(TT + 255) / 256, 256, 0, sA>>>();
    cudaEventRecord(evA, sA);

    // branch B: w2 convert + out memset — hidden under GEMM1
    {
        int w4 = NE * ID * HD / 4;
        to_half_kernel<<<(w4 + 511) / 512, 256, 0, sB>>>((const float4*)w2, (uint2*)w2_p, w4);
        cudaMemsetAsync(d_out, 0, (size_t)out_size * sizeof(float), sB);
        cudaEventRecord(evB, sB);
    }

    // main stream: only the x convert precedes GEMM1 now
    {
        int n4 = TT * HD / 4;
        to_half_kernel<<<(n4 + 511) / 512, 256>>>((const float4*)hidden, (uint2*)xh_p, n4);
    }

    // join routing -> GEMM1 (reads fp32 w1/w3 directly, converts in-register)
    cudaStreamWaitEvent(0, evA, 0);
    gemm1_mma_kernel<<<dim3(GRID_X, ID / 64, 1), 256, GEMM1_SMEM>>>(w1, w3);

    // join w2 convert + memset -> GEMM2
    cudaStreamWaitEvent(0, evB, 0);
    gemm2_mma_kernel<<<dim3(GRID_X, HD / 128, 1), 256, GEMM2_SMEM>>>(out);
}

// round 14
// speedup vs baseline: 1.1752x; 1.1752x over previous
#include <cuda_runtime.h>
#include <cuda_fp16.h>
#include <cstdint>
#include <math.h>

#define TT 8192
#define NE 8
#define HD 2048
#define ID 5632
#define NROW (TT*2)

// ---------------- scratch (static device globals) ----------------
__device__ int    g_count[NE];
__device__ int    g_base[NE];
__device__ int    g_ctr[NE];
__device__ int    g_blkbase[NE + 1];
__device__ int    g_tok_e[TT*2];
__device__ float  g_tok_w[TT*2];
__device__ int    g_row_of[TT*2];
__device__ int    g_tok_of_row[NROW];
__device__ float  g_w_of_row[NROW];
__device__ __half g_xh [(size_t)TT*HD];
__device__ __half g_w1h[(size_t)NE*ID*HD];
__device__ __half g_w3h[(size_t)NE*ID*HD];
__device__ __half g_w2h[(size_t)NE*HD*ID];
__device__ __half g_act[(size_t)NROW*ID];

// ---------------- helpers ----------------
__device__ __forceinline__ void cpa16(uint32_t dst, uint64_t gsrc) {
    asm volatile("cp.async.cg.shared.global [%0], [%1], 16;" :: "r"(dst), "l"(gsrc));
}
#define CPA_COMMIT() asm volatile("cp.async.commit_group;" ::: "memory")
#define CPA_WAIT(n)  asm volatile("cp.async.wait_group %0;" :: "n"(n) : "memory")

__device__ __forceinline__ uint32_t smem_u32(const void* p) {
    uint32_t a;
    asm("{ .reg .u64 t; cvta.to.shared.u64 t, %1; cvt.u32.u64 %0, t; }" : "=r"(a) : "l"(p));
    return a;
}

__device__ __forceinline__ void mma_f16(float* c, const uint32_t* a, const uint32_t* b) {
    asm volatile(
        "mma.sync.aligned.m16n8k16.row.col.f32.f16.f16.f32 "
        "{%0,%1,%2,%3},{%4,%5,%6,%7},{%8,%9},{%0,%1,%2,%3};"
        : "+f"(c[0]), "+f"(c[1]), "+f"(c[2]), "+f"(c[3])
        : "r"(a[0]), "r"(a[1]), "r"(a[2]), "r"(a[3]), "r"(b[0]), "r"(b[1]));
}

// ---------------- routing ----------------
__global__ void zero_meta_kernel() { if (threadIdx.x < NE) g_count[threadIdx.x] = 0; }

__global__ void route_count_kernel(const float* __restrict__ logits) {
    int t = blockIdx.x * blockDim.x + threadIdx.x;
    if (t >= TT) return;
    float v[NE];
#pragma unroll
    for (int e = 0; e < NE; e++) v[e] = logits[t * NE + e];
    int i0 = 0; float m0 = v[0];
#pragma unroll
    for (int e = 1; e < NE; e++) if (v[e] > m0) { m0 = v[e]; i0 = e; }
    int i1 = -1; float m1 = -INFINITY;
#pragma unroll
    for (int e = 0; e < NE; e++) if (e != i0 && v[e] > m1) { m1 = v[e]; i1 = e; }
    float z = expf(m1 - m0);
    float w0 = 1.0f / (1.0f + z);
    g_tok_e[t*2+0] = i0; g_tok_e[t*2+1] = i1;
    g_tok_w[t*2+0] = w0; g_tok_w[t*2+1] = z * w0;
    atomicAdd(&g_count[i0], 1);
    atomicAdd(&g_count[i1], 1);
}

__global__ void scan_kernel() {
    int acc = 0, pb = 0;
    for (int e = 0; e < NE; e++) {
        g_base[e] = acc; acc += g_count[e]; g_ctr[e] = 0;
        g_blkbase[e] = pb; pb += (g_count[e] + 127) >> 7;
    }
    g_blkbase[NE] = pb;
}

__global__ void route_scatter_kernel() {
    int t = blockIdx.x * blockDim.x + threadIdx.x;
    if (t >= TT) return;
#pragma unroll
    for (int k = 0; k < 2; k++) {
        int e = g_tok_e[t*2+k];
        int slot = atomicAdd(&g_ctr[e], 1);
        int row = g_base[e] + slot;
        g_row_of[t*2+k] = row;
        g_tok_of_row[row] = t;
        g_w_of_row[row] = g_tok_w[t*2+k];
    }
}

// ---------------- fp32 -> fp16 convert (4 independent float4 per thread, MLP=4) ----------------
__global__ void to_half_kernel(const float4* __restrict__ in, uint2* __restrict__ out, int n4) {
    int i = (blockIdx.x * blockDim.x + threadIdx.x) * 4;
    if (i + 3 < n4) {
        float4 v0 = in[i + 0];
        float4 v1 = in[i + 1];
        float4 v2 = in[i + 2];
        float4 v3 = in[i + 3];
#pragma unroll
        for (int q = 0; q < 4; q++) {
            float4 v = (q == 0) ? v0 : (q == 1) ? v1 : (q == 2) ? v2 : v3;
            __half2 h0 = __floats2half2_rn(v.x, v.y);
            __half2 h1 = __floats2half2_rn(v.z, v.w);
            uint2 o;
            o.x = *reinterpret_cast<uint32_t*>(&h0);
            o.y = *reinterpret_cast<uint32_t*>(&h1);
            out[i + q] = o;
        }
    } else {
        for (int j = i; j < n4; j++) {
            float4 v = in[j];
            __half2 h0 = __floats2half2_rn(v.x, v.y);
            __half2 h1 = __floats2half2_rn(v.z, v.w);
            uint2 o;
            o.x = *reinterpret_cast<uint32_t*>(&h0);
            o.y = *reinterpret_cast<uint32_t*>(&h1);
            out[j] = o;
        }
    }
}

// ---------------- GEMM kernels (fp16 m16n8k16, R10 core — DO NOT PERTURB) ----------------
#define BKH  32
#define PFH  40
#define TILE_H (128*PFH)                  // halves per tile per stage (5120)
#define STG_B  (TILE_H*2)                 // 10240 bytes
#define NSTG 4
#define GEMM_SMEM (2*NSTG*STG_B)          // 81920 bytes
#define GRID_X (NROW/128 + NE)            // packed block bound (136)

// GEMM1: B rows 0..63 = w1 rows (gate), 64..127 = w3 rows (up), same 64 I-cols.
__global__ void __launch_bounds__(256, 2) gemm1_mma_kernel() {
    extern __shared__ char sm[];
    char* AsB = sm;
    char* BsB = sm + NSTG * STG_B;

    const int bx = blockIdx.x;
    if (bx >= g_blkbase[NE]) return;
    int e = 0;
#pragma unroll
    for (int k = 1; k < NE; k++) if (bx >= g_blkbase[k]) e = k;
    const int row0 = (bx - g_blkbase[e]) * 128;
    const int cnt = g_count[e];
    const int base = g_base[e];
    const int nI = blockIdx.y * 64;

    const int tid  = threadIdx.x;
    const int warp = tid >> 5;
    const int lane = tid & 31;
    const int wm = warp & 1;
    const int wn = warp >> 1;
    const int g  = lane >> 2;
    const int tg = lane & 3;

    const int lrow = tid >> 1;
    const int lcol = (tid & 1) * 16;

    int gr = row0 + lrow;
    int tok = (gr < cnt) ? g_tok_of_row[base + gr] : 0;
    const uint64_t aG = (uint64_t)__cvta_generic_to_global(g_xh + (size_t)tok * HD + lcol);
    const __half* bptr = (lrow < 64)
        ? g_w1h + ((size_t)e * ID + nI + lrow) * HD + lcol
        : g_w3h + ((size_t)e * ID + nI + (lrow - 64)) * HD + lcol;
    const uint64_t bG = (uint64_t)__cvta_generic_to_global(bptr);

    const uint32_t aS = smem_u32(AsB) + (uint32_t)(lrow * PFH + lcol) * 2;
    const uint32_t bS = smem_u32(BsB) + (uint32_t)(lrow * PFH + lcol) * 2;

    float acc[4][4][4];
#pragma unroll
    for (int i = 0; i < 4; i++)
#pragma unroll
        for (int j = 0; j < 4; j++)
#pragma unroll
            for (int q = 0; q < 4; q++) acc[i][j][q] = 0.f;

    const int NS = HD / BKH;  // 64
#pragma unroll
    for (int p = 0; p < NSTG - 1; p++) {
        uint32_t so = p * STG_B;
        uint64_t ko = (uint64_t)p * BKH * 2;
        cpa16(aS + so, aG + ko); cpa16(aS + so + 16, aG + ko + 16);
        cpa16(bS + so, bG + ko); cpa16(bS + so + 16, bG + ko + 16);
        CPA_COMMIT();
    }

    for (int s = 0; s < NS; s++) {
        CPA_WAIT(NSTG - 2);
        __syncthreads();
        if (s + NSTG - 1 < NS) {
            uint32_t so = ((s + NSTG - 1) & (NSTG - 1)) * STG_B;
            uint64_t ko = (uint64_t)(s + NSTG - 1) * BKH * 2;
            cpa16(aS + so, aG + ko); cpa16(aS + so + 16, aG + ko + 16);
            cpa16(bS + so, bG + ko); cpa16(bS + so + 16, bG + ko + 16);
        }
        CPA_COMMIT();

        const uint32_t* A = (const uint32_t*)(AsB + (s & (NSTG - 1)) * STG_B);
        const uint32_t* B = (const uint32_t*)(BsB + (s & (NSTG - 1)) * STG_B);
#pragma unroll
        for (int kc = 0; kc < 2; kc++) {
            uint32_t a[4][4], b[4][2];
            const int kb = kc * 8;
#pragma unroll
            for (int mf = 0; mf < 4; mf++) {
                int mb = wm * 64 + mf * 16 + g;
                a[mf][0] = A[mb * 20 + kb + tg];
                a[mf][1] = A[(mb + 8) * 20 + kb + tg];
                a[mf][2] = A[mb * 20 + kb + tg + 4];
                a[mf][3] = A[(mb + 8) * 20 + kb + tg + 4];
            }
#pragma unroll
            for (int nf = 0; nf < 4; nf++) {
                int nb = wn * 32 + nf * 8 + g;
                b[nf][0] = B[nb * 20 + kb + tg];
                b[nf][1] = B[nb * 20 + kb + tg + 4];
            }
#pragma unroll
            for (int mf = 0; mf < 4; mf++)
#pragma unroll
                for (int nf = 0; nf < 4; nf++) mma_f16(acc[mf][nf], a[mf], b[nf]);
        }
    }
    __syncthreads();

    // epilogue: up warps (wn>=2) stage accums via smem; gate warps apply silu*up
    float* up_s = (float*)sm;
    if (wn >= 2) {
#pragma unroll
        for (int mf = 0; mf < 4; mf++) {
#pragma unroll
            for (int nf = 0; nf < 4; nf++) {
                int r = wm * 64 + mf * 16 + g;
                int c = (wn - 2) * 32 + nf * 8 + 2 * tg;
                up_s[r * 65 + c]           = acc[mf][nf][0];
                up_s[r * 65 + c + 1]       = acc[mf][nf][1];
                up_s[(r + 8) * 65 + c]     = acc[mf][nf][2];
                up_s[(r + 8) * 65 + c + 1] = acc[mf][nf][3];
            }
        }
    }
    __syncthreads();
    if (wn < 2) {
#pragma unroll
        for (int mf = 0; mf < 4; mf++) {
#pragma unroll
            for (int nf = 0; nf < 4; nf++) {
                int r = wm * 64 + mf * 16 + g;
                int c = wn * 32 + nf * 8 + 2 * tg;
#pragma unroll
                for (int half = 0; half < 2; half++) {
                    int rr = r + half * 8;
                    int grow = row0 + rr;
                    if (grow >= cnt) continue;
                    float gv0 = acc[mf][nf][half * 2 + 0];
                    float gv1 = acc[mf][nf][half * 2 + 1];
                    float u0 = up_s[rr * 65 + c];
                    float u1 = up_s[rr * 65 + c + 1];
                    float s0 = gv0 / (1.0f + __expf(-gv0));
                    float s1 = gv1 / (1.0f + __expf(-gv1));
                    __half2 h = __floats2half2_rn(s0 * u0, s1 * u1);
                    *(__half2*)(g_act + (size_t)(base + grow) * ID + nI + c) = h;
                }
            }
        }
    }
}

// GEMM2: out[tok] += w_row * (act @ w2^T) — combine fused via atomicAdd.
__global__ void __launch_bounds__(256, 2) gemm2_mma_kernel(float* __restrict__ out) {
    extern __shared__ char sm[];
    char* AsB = sm;
    char* BsB = sm + NSTG * STG_B;

    const int bx = blockIdx.x;
    if (bx >= g_blkbase[NE]) return;
    int e = 0;
#pragma unroll
    for (int k = 1; k < NE; k++) if (bx >= g_blkbase[k]) e = k;
    const int row0 = (bx - g_blkbase[e]) * 128;
    const int cnt = g_count[e];
    const int base = g_base[e];
    const int n0b = blockIdx.y * 128;

    const int tid  = threadIdx.x;
    const int warp = tid >> 5;
    const int lane = tid & 31;
    const int wm = warp & 1;
    const int wn = warp >> 1;
    const int g  = lane >> 2;
    const int tg = lane & 3;

    const int lrow = tid >> 1;
    const int lcol = (tid & 1) * 16;

    int gr = row0 + lrow; if (gr >= cnt) gr = cnt - 1;
    const uint64_t aG = (uint64_t)__cvta_generic_to_global(g_act + (size_t)(base + gr) * ID + lcol);
    const uint64_t bG = (uint64_t)__cvta_generic_to_global(g_w2h + ((size_t)e * HD + n0b + lrow) * ID + lcol);

    const uint32_t aS = smem_u32(AsB) + (uint32_t)(lrow * PFH + lcol) * 2;
    const uint32_t bS = smem_u32(BsB) + (uint32_t)(lrow * PFH + lcol) * 2;

    float acc[4][4][4];
#pragma unroll
    for (int i = 0; i < 4; i++)
#pragma unroll
        for (int j = 0; j < 4; j++)
#pragma unroll
            for (int q = 0; q < 4; q++) acc[i][j][q] = 0.f;

    const int NS = ID / BKH;  // 176
#pragma unroll
    for (int p = 0; p < NSTG - 1; p++) {
        uint32_t so = p * STG_B;
        uint64_t ko = (uint64_t)p * BKH * 2;
        cpa16(aS + so, aG + ko); cpa16(aS + so + 16, aG + ko + 16);
        cpa16(bS + so, bG + ko); cpa16(bS + so + 16, bG + ko + 16);
        CPA_COMMIT();
    }

    for (int s = 0; s < NS; s++) {
        CPA_WAIT(NSTG - 2);
        __syncthreads();
        if (s + NSTG - 1 < NS) {
            uint32_t so = ((s + NSTG - 1) & (NSTG - 1)) * STG_B;
            uint64_t ko = (uint64_t)(s + NSTG - 1) * BKH * 2;
            cpa16(aS + so, aG + ko); cpa16(aS + so + 16, aG + ko + 16);
            cpa16(bS + so, bG + ko); cpa16(bS + so + 16, bG + ko + 16);
        }
        CPA_COMMIT();

        const uint32_t* A = (const uint32_t*)(AsB + (s & (NSTG - 1)) * STG_B);
        const uint32_t* B = (const uint32_t*)(BsB + (s & (NSTG - 1)) * STG_B);
#pragma unroll
        for (int kc = 0; kc < 2; kc++) {
            uint32_t a[4][4], b[4][2];
            const int kb = kc * 8;
#pragma unroll
            for (int mf = 0; mf < 4; mf++) {
                int mb = wm * 64 + mf * 16 + g;
                a[mf][0] = A[mb * 20 + kb + tg];
                a[mf][1] = A[(mb + 8) * 20 + kb + tg];
                a[mf][2] = A[mb * 20 + kb + tg + 4];
                a[mf][3] = A[(mb + 8) * 20 + kb + tg + 4];
            }
#pragma unroll
            for (int nf = 0; nf < 4; nf++) {
                int nb = wn * 32 + nf * 8 + g;
                b[nf][0] = B[nb * 20 + kb + tg];
                b[nf][1] = B[nb * 20 + kb + tg + 4];
            }
#pragma unroll
            for (int mf = 0; mf < 4; mf++)
#pragma unroll
                for (int nf = 0; nf < 4; nf++) mma_f16(acc[mf][nf], a[mf], b[nf]);
        }
    }

#pragma unroll
    for (int mf = 0; mf < 4; mf++) {
#pragma unroll
        for (int nf = 0; nf < 4; nf++) {
            int r = wm * 64 + mf * 16 + g;
            int c = wn * 32 + nf * 8 + 2 * tg;
#pragma unroll
            for (int half = 0; half < 2; half++) {
                int rr = r + half * 8;
                int grow = row0 + rr;
                if (grow >= cnt) continue;
                int tok2 = g_tok_of_row[base + grow];
                float wr = g_w_of_row[base + grow];
                float* op = out + (size_t)tok2 * HD + n0b + c;
                atomicAdd(op,     wr * acc[mf][nf][half * 2 + 0]);
                atomicAdd(op + 1, wr * acc[mf][nf][half * 2 + 1]);
            }
        }
    }
}

// ---------------- launch (R10 fork-join schedule) ----------------
extern "C" void kernel_launch(void* const* d_in, const int* in_sizes, int n_in,
                              void* d_out, int out_size)
{
    const float* hidden = (const float*)d_in[0];
    const float* logits = (const float*)d_in[1];
    const float* w1 = (const float*)d_in[2];
    const float* w2 = (const float*)d_in[3];
    const float* w3 = (const float*)d_in[4];
    float* out = (float*)d_out;

    static int init_done = 0;
    static cudaStream_t sA, sB;
    static cudaEvent_t evRoot, evA, evB;
    if (!init_done) {
        cudaFuncSetAttribute(gemm1_mma_kernel, cudaFuncAttributeMaxDynamicSharedMemorySize, GEMM_SMEM);
        cudaFuncSetAttribute(gemm2_mma_kernel, cudaFuncAttributeMaxDynamicSharedMemorySize, GEMM_SMEM);
        cudaStreamCreateWithFlags(&sA, cudaStreamNonBlocking);
        cudaStreamCreateWithFlags(&sB, cudaStreamNonBlocking);
        cudaEventCreateWithFlags(&evRoot, cudaEventDisableTiming);
        cudaEventCreateWithFlags(&evA, cudaEventDisableTiming);
        cudaEventCreateWithFlags(&evB, cudaEventDisableTiming);
        init_done = 1;
    }

    __half *xh_p, *w1_p, *w2_p, *w3_p;
    cudaGetSymbolAddress((void**)&xh_p, g_xh);
    cudaGetSymbolAddress((void**)&w1_p, g_w1h);
    cudaGetSymbolAddress((void**)&w2_p, g_w2h);
    cudaGetSymbolAddress((void**)&w3_p, g_w3h);

    // fork
    cudaEventRecord(evRoot, 0);
    cudaStreamWaitEvent(sA, evRoot, 0);
    cudaStreamWaitEvent(sB, evRoot, 0);

    // branch A: routing chain — hidden under the main-stream converts
    zero_meta_kernel<<<1, 32, 0, sA>>>();
    route_count_kernel<<<(TT + 255) / 256, 256, 0, sA>>>(logits);
    scan_kernel<<<1, 1, 0, sA>>>();
    route_scatter_kernel<<<(TT + 255) / 256, 256, 0, sA>>>();
    cudaEventRecord(evA, sA);

    // branch B: w2 convert + out memset — hidden under GEMM1
    {
        int w4 = NE * ID * HD / 4;
        to_half_kernel<<<(w4 + 1023) / 1024, 256, 0, sB>>>((const float4*)w2, (uint2*)w2_p, w4);
        cudaMemsetAsync(d_out, 0, (size_t)out_size * sizeof(float), sB);
        cudaEventRecord(evB, sB);
    }

    // main stream: converts needed by GEMM1
    {
        int n4 = TT * HD / 4;
        to_half_kernel<<<(n4 + 1023) / 1024, 256>>>((const float4*)hidden, (uint2*)xh_p, n4);
        int w4 = NE * ID * HD / 4;
        to_half_kernel<<<(w4 + 1023) / 1024, 256>>>((const float4*)w1, (uint2*)w1_p, w4);
        to_half_kernel<<<(w4 + 1023) / 1024, 256>>>((const float4*)w3, (uint2*)w3_p, w4);
    }

    // join routing -> GEMM1
    cudaStreamWaitEvent(0, evA, 0);
    gemm1_mma_kernel<<<dim3(GRID_X, ID / 64, 1), 256, GEMM_SMEM>>>();

    // join w2 convert + memset -> GEMM2
    cudaStreamWaitEvent(0, evB, 0);
    gemm2_mma_kernel<<<dim3(GRID_X, HD / 128, 1), 256, GEMM_SMEM>>>(out);
}

// round 16
// speedup vs baseline: 1.1876x; 1.0105x over previous
#include <cuda_runtime.h>
#include <cuda_fp16.h>
#include <cstdint>
#include <math.h>

#define TT 8192
#define NE 8
#define HD 2048
#define ID 5632
#define NROW (TT*2)

// ---------------- scratch (static device globals) ----------------
__device__ int    g_count[NE];
__device__ int    g_base[NE];
__device__ int    g_ctr[NE];
__device__ int    g_blkbase[NE + 1];
__device__ int    g_tok_e[TT*2];
__device__ float  g_tok_w[TT*2];
__device__ int    g_row_of[TT*2];
__device__ int    g_tok_of_row[NROW];
__device__ float  g_w_of_row[NROW];
__device__ __half g_xh [(size_t)TT*HD];
__device__ __half g_w1h[(size_t)NE*ID*HD];
__device__ __half g_w3h[(size_t)NE*ID*HD];
__device__ __half g_w2h[(size_t)NE*HD*ID];
__device__ __half g_act[(size_t)NROW*ID];

// ---------------- helpers ----------------
__device__ __forceinline__ void cpa16(uint32_t dst, uint64_t gsrc) {
    asm volatile("cp.async.cg.shared.global [%0], [%1], 16;" :: "r"(dst), "l"(gsrc));
}
#define CPA_COMMIT() asm volatile("cp.async.commit_group;" ::: "memory")
#define CPA_WAIT(n)  asm volatile("cp.async.wait_group %0;" :: "n"(n) : "memory")

__device__ __forceinline__ uint32_t smem_u32(const void* p) {
    uint32_t a;
    asm("{ .reg .u64 t; cvta.to.shared.u64 t, %1; cvt.u32.u64 %0, t; }" : "=r"(a) : "l"(p));
    return a;
}

__device__ __forceinline__ void mma_f16(float* c, const uint32_t* a, const uint32_t* b) {
    asm volatile(
        "mma.sync.aligned.m16n8k16.row.col.f32.f16.f16.f32 "
        "{%0,%1,%2,%3},{%4,%5,%6,%7},{%8,%9},{%0,%1,%2,%3};"
        : "+f"(c[0]), "+f"(c[1]), "+f"(c[2]), "+f"(c[3])
        : "r"(a[0]), "r"(a[1]), "r"(a[2]), "r"(a[3]), "r"(b[0]), "r"(b[1]));
}

// ---------------- routing ----------------
__global__ void zero_meta_kernel() { if (threadIdx.x < NE) g_count[threadIdx.x] = 0; }

__global__ void route_count_kernel(const float* __restrict__ logits) {
    int t = blockIdx.x * blockDim.x + threadIdx.x;
    if (t >= TT) return;
    float v[NE];
#pragma unroll
    for (int e = 0; e < NE; e++) v[e] = logits[t * NE + e];
    int i0 = 0; float m0 = v[0];
#pragma unroll
    for (int e = 1; e < NE; e++) if (v[e] > m0) { m0 = v[e]; i0 = e; }
    int i1 = -1; float m1 = -INFINITY;
#pragma unroll
    for (int e = 0; e < NE; e++) if (e != i0 && v[e] > m1) { m1 = v[e]; i1 = e; }
    float z = expf(m1 - m0);
    float w0 = 1.0f / (1.0f + z);
    g_tok_e[t*2+0] = i0; g_tok_e[t*2+1] = i1;
    g_tok_w[t*2+0] = w0; g_tok_w[t*2+1] = z * w0;
    atomicAdd(&g_count[i0], 1);
    atomicAdd(&g_count[i1], 1);
}

__global__ void scan_kernel() {
    int acc = 0, pb = 0;
    for (int e = 0; e < NE; e++) {
        g_base[e] = acc; acc += g_count[e]; g_ctr[e] = 0;
        g_blkbase[e] = pb; pb += (g_count[e] + 127) >> 7;
    }
    g_blkbase[NE] = pb;
}

__global__ void route_scatter_kernel() {
    int t = blockIdx.x * blockDim.x + threadIdx.x;
    if (t >= TT) return;
#pragma unroll
    for (int k = 0; k < 2; k++) {
        int e = g_tok_e[t*2+k];
        int slot = atomicAdd(&g_ctr[e], 1);
        int row = g_base[e] + slot;
        g_row_of[t*2+k] = row;
        g_tok_of_row[row] = t;
        g_w_of_row[row] = g_tok_w[t*2+k];
    }
}

// ---------------- fp32 -> fp16 converts ----------------
__device__ __forceinline__ uint2 cvt_f4(float4 v) {
    __half2 h0 = __floats2half2_rn(v.x, v.y);
    __half2 h1 = __floats2half2_rn(v.z, v.w);
    uint2 o;
    o.x = *reinterpret_cast<uint32_t*>(&h0);
    o.y = *reinterpret_cast<uint32_t*>(&h1);
    return o;
}

// single-tensor convert (2 float4 per thread — R10-measured optimum)
__global__ void to_half_kernel(const float4* __restrict__ in, uint2* __restrict__ out, int n4) {
    int i = (blockIdx.x * blockDim.x + threadIdx.x) * 2;
#pragma unroll
    for (int q = 0; q < 2; q++) {
        int j = i + q;
        if (j >= n4) return;
        out[j] = cvt_f4(in[j]);
    }
}

// merged x + w1 + w3 convert over concatenated index space (2 float4 per thread)
#define NX4 (TT*HD/4)          // 4,194,304
#define NW4 (NE*ID*HD/4)       // 23,068,672
__global__ void conv3_kernel(const float4* __restrict__ x,  uint2* __restrict__ xo,
                             const float4* __restrict__ w1, uint2* __restrict__ w1o,
                             const float4* __restrict__ w3, uint2* __restrict__ w3o) {
    long long i = ((long long)blockIdx.x * blockDim.x + threadIdx.x) * 2;
#pragma unroll
    for (int q = 0; q < 2; q++) {
        long long j = i + q;
        if (j < NX4) {
            xo[j] = cvt_f4(x[j]);
        } else if (j < (long long)NX4 + NW4) {
            long long o = j - NX4;
            w1o[o] = cvt_f4(w1[o]);
        } else if (j < (long long)NX4 + 2LL * NW4) {
            long long o = j - NX4 - NW4;
            w3o[o] = cvt_f4(w3[o]);
        } else return;
    }
}

// ---------------- GEMM kernels (fp16 m16n8k16, R10 core — DO NOT PERTURB) ----------------
#define BKH  32
#define PFH  40
#define TILE_H (128*PFH)
#define STG_B  (TILE_H*2)
#define NSTG 4
#define GEMM_SMEM (2*NSTG*STG_B)
#define GRID_X (NROW/128 + NE)

// GEMM1: B rows 0..63 = w1 rows (gate), 64..127 = w3 rows (up), same 64 I-cols.
__global__ void __launch_bounds__(256, 2) gemm1_mma_kernel() {
    extern __shared__ char sm[];
    char* AsB = sm;
    char* BsB = sm + NSTG * STG_B;

    const int bx = blockIdx.x;
    if (bx >= g_blkbase[NE]) return;
    int e = 0;
#pragma unroll
    for (int k = 1; k < NE; k++) if (bx >= g_blkbase[k]) e = k;
    const int row0 = (bx - g_blkbase[e]) * 128;
    const int cnt = g_count[e];
    const int base = g_base[e];
    const int nI = blockIdx.y * 64;

    const int tid  = threadIdx.x;
    const int warp = tid >> 5;
    const int lane = tid & 31;
    const int wm = warp & 1;
    const int wn = warp >> 1;
    const int g  = lane >> 2;
    const int tg = lane & 3;

    const int lrow = tid >> 1;
    const int lcol = (tid & 1) * 16;

    int gr = row0 + lrow;
    int tok = (gr < cnt) ? g_tok_of_row[base + gr] : 0;
    const uint64_t aG = (uint64_t)__cvta_generic_to_global(g_xh + (size_t)tok * HD + lcol);
    const __half* bptr = (lrow < 64)
        ? g_w1h + ((size_t)e * ID + nI + lrow) * HD + lcol
        : g_w3h + ((size_t)e * ID + nI + (lrow - 64)) * HD + lcol;
    const uint64_t bG = (uint64_t)__cvta_generic_to_global(bptr);

    const uint32_t aS = smem_u32(AsB) + (uint32_t)(lrow * PFH + lcol) * 2;
    const uint32_t bS = smem_u32(BsB) + (uint32_t)(lrow * PFH + lcol) * 2;

    float acc[4][4][4];
#pragma unroll
    for (int i = 0; i < 4; i++)
#pragma unroll
        for (int j = 0; j < 4; j++)
#pragma unroll
            for (int q = 0; q < 4; q++) acc[i][j][q] = 0.f;

    const int NS = HD / BKH;  // 64
#pragma unroll
    for (int p = 0; p < NSTG - 1; p++) {
        uint32_t so = p * STG_B;
        uint64_t ko = (uint64_t)p * BKH * 2;
        cpa16(aS + so, aG + ko); cpa16(aS + so + 16, aG + ko + 16);
        cpa16(bS + so, bG + ko); cpa16(bS + so + 16, bG + ko + 16);
        CPA_COMMIT();
    }

    for (int s = 0; s < NS; s++) {
        CPA_WAIT(NSTG - 2);
        __syncthreads();
        if (s + NSTG - 1 < NS) {
            uint32_t so = ((s + NSTG - 1) & (NSTG - 1)) * STG_B;
            uint64_t ko = (uint64_t)(s + NSTG - 1) * BKH * 2;
            cpa16(aS + so, aG + ko); cpa16(aS + so + 16, aG + ko + 16);
            cpa16(bS + so, bG + ko); cpa16(bS + so + 16, bG + ko + 16);
        }
        CPA_COMMIT();

        const uint32_t* A = (const uint32_t*)(AsB + (s & (NSTG - 1)) * STG_B);
        const uint32_t* B = (const uint32_t*)(BsB + (s & (NSTG - 1)) * STG_B);
#pragma unroll
        for (int kc = 0; kc < 2; kc++) {
            uint32_t a[4][4], b[4][2];
            const int kb = kc * 8;
#pragma unroll
            for (int mf = 0; mf < 4; mf++) {
                int mb = wm * 64 + mf * 16 + g;
                a[mf][0] = A[mb * 20 + kb + tg];
                a[mf][1] = A[(mb + 8) * 20 + kb + tg];
                a[mf][2] = A[mb * 20 + kb + tg + 4];
                a[mf][3] = A[(mb + 8) * 20 + kb + tg + 4];
            }
#pragma unroll
            for (int nf = 0; nf < 4; nf++) {
                int nb = wn * 32 + nf * 8 + g;
                b[nf][0] = B[nb * 20 + kb + tg];
                b[nf][1] = B[nb * 20 + kb + tg + 4];
            }
#pragma unroll
            for (int mf = 0; mf < 4; mf++)
#pragma unroll
                for (int nf = 0; nf < 4; nf++) mma_f16(acc[mf][nf], a[mf], b[nf]);
        }
    }
    __syncthreads();

    float* up_s = (float*)sm;
    if (wn >= 2) {
#pragma unroll
        for (int mf = 0; mf < 4; mf++) {
#pragma unroll
            for (int nf = 0; nf < 4; nf++) {
                int r = wm * 64 + mf * 16 + g;
                int c = (wn - 2) * 32 + nf * 8 + 2 * tg;
                up_s[r * 65 + c]           = acc[mf][nf][0];
                up_s[r * 65 + c + 1]       = acc[mf][nf][1];
                up_s[(r + 8) * 65 + c]     = acc[mf][nf][2];
                up_s[(r + 8) * 65 + c + 1] = acc[mf][nf][3];
            }
        }
    }
    __syncthreads();
    if (wn < 2) {
#pragma unroll
        for (int mf = 0; mf < 4; mf++) {
#pragma unroll
            for (int nf = 0; nf < 4; nf++) {
                int r = wm * 64 + mf * 16 + g;
                int c = wn * 32 + nf * 8 + 2 * tg;
#pragma unroll
                for (int half = 0; half < 2; half++) {
                    int rr = r + half * 8;
                    int grow = row0 + rr;
                    if (grow >= cnt) continue;
                    float gv0 = acc[mf][nf][half * 2 + 0];
                    float gv1 = acc[mf][nf][half * 2 + 1];
                    float u0 = up_s[rr * 65 + c];
                    float u1 = up_s[rr * 65 + c + 1];
                    float s0 = gv0 / (1.0f + __expf(-gv0));
                    float s1 = gv1 / (1.0f + __expf(-gv1));
                    __half2 h = __floats2half2_rn(s0 * u0, s1 * u1);
                    *(__half2*)(g_act + (size_t)(base + grow) * ID + nI + c) = h;
                }
            }
        }
    }
}

// GEMM2: out[tok] += w_row * (act @ w2^T) — combine fused via atomicAdd.
__global__ void __launch_bounds__(256, 2) gemm2_mma_kernel(float* __restrict__ out) {
    extern __shared__ char sm[];
    char* AsB = sm;
    char* BsB = sm + NSTG * STG_B;

    const int bx = blockIdx.x;
    if (bx >= g_blkbase[NE]) return;
    int e = 0;
#pragma unroll
    for (int k = 1; k < NE; k++) if (bx >= g_blkbase[k]) e = k;
    const int row0 = (bx - g_blkbase[e]) * 128;
    const int cnt = g_count[e];
    const int base = g_base[e];
    const int n0b = blockIdx.y * 128;

    const int tid  = threadIdx.x;
    const int warp = tid >> 5;
    const int lane = tid & 31;
    const int wm = warp & 1;
    const int wn = warp >> 1;
    const int g  = lane >> 2;
    const int tg = lane & 3;

    const int lrow = tid >> 1;
    const int lcol = (tid & 1) * 16;

    int gr = row0 + lrow; if (gr >= cnt) gr = cnt - 1;
    const uint64_t aG = (uint64_t)__cvta_generic_to_global(g_act + (size_t)(base + gr) * ID + lcol);
    const uint64_t bG = (uint64_t)__cvta_generic_to_global(g_w2h + ((size_t)e * HD + n0b + lrow) * ID + lcol);

    const uint32_t aS = smem_u32(AsB) + (uint32_t)(lrow * PFH + lcol) * 2;
    const uint32_t bS = smem_u32(BsB) + (uint32_t)(lrow * PFH + lcol) * 2;

    float acc[4][4][4];
#pragma unroll
    for (int i = 0; i < 4; i++)
#pragma unroll
        for (int j = 0; j < 4; j++)
#pragma unroll
            for (int q = 0; q < 4; q++) acc[i][j][q] = 0.f;

    const int NS = ID / BKH;  // 176
#pragma unroll
    for (int p = 0; p < NSTG - 1; p++) {
        uint32_t so = p * STG_B;
        uint64_t ko = (uint64_t)p * BKH * 2;
        cpa16(aS + so, aG + ko); cpa16(aS + so + 16, aG + ko + 16);
        cpa16(bS + so, bG + ko); cpa16(bS + so + 16, bG + ko + 16);
        CPA_COMMIT();
    }

    for (int s = 0; s < NS; s++) {
        CPA_WAIT(NSTG - 2);
        __syncthreads();
        if (s + NSTG - 1 < NS) {
            uint32_t so = ((s + NSTG - 1) & (NSTG - 1)) * STG_B;
            uint64_t ko = (uint64_t)(s + NSTG - 1) * BKH * 2;
            cpa16(aS + so, aG + ko); cpa16(aS + so + 16, aG + ko + 16);
            cpa16(bS + so, bG + ko); cpa16(bS + so + 16, bG + ko + 16);
        }
        CPA_COMMIT();

        const uint32_t* A = (const uint32_t*)(AsB + (s & (NSTG - 1)) * STG_B);
        const uint32_t* B = (const uint32_t*)(BsB + (s & (NSTG - 1)) * STG_B);
#pragma unroll
        for (int kc = 0; kc < 2; kc++) {
            uint32_t a[4][4], b[4][2];
            const int kb = kc * 8;
#pragma unroll
            for (int mf = 0; mf < 4; mf++) {
                int mb = wm * 64 + mf * 16 + g;
                a[mf][0] = A[mb * 20 + kb + tg];
                a[mf][1] = A[(mb + 8) * 20 + kb + tg];
                a[mf][2] = A[mb * 20 + kb + tg + 4];
                a[mf][3] = A[(mb + 8) * 20 + kb + tg + 4];
            }
#pragma unroll
            for (int nf = 0; nf < 4; nf++) {
                int nb = wn * 32 + nf * 8 + g;
                b[nf][0] = B[nb * 20 + kb + tg];
                b[nf][1] = B[nb * 20 + kb + tg + 4];
            }
#pragma unroll
            for (int mf = 0; mf < 4; mf++)
#pragma unroll
                for (int nf = 0; nf < 4; nf++) mma_f16(acc[mf][nf], a[mf], b[nf]);
        }
    }

#pragma unroll
    for (int mf = 0; mf < 4; mf++) {
#pragma unroll
        for (int nf = 0; nf < 4; nf++) {
            int r = wm * 64 + mf * 16 + g;
            int c = wn * 32 + nf * 8 + 2 * tg;
#pragma unroll
            for (int half = 0; half < 2; half++) {
                int rr = r + half * 8;
                int grow = row0 + rr;
                if (grow >= cnt) continue;
                int tok2 = g_tok_of_row[base + grow];
                float wr = g_w_of_row[base + grow];
                float* op = out + (size_t)tok2 * HD + n0b + c;
                atomicAdd(op,     wr * acc[mf][nf][half * 2 + 0]);
                atomicAdd(op + 1, wr * acc[mf][nf][half * 2 + 1]);
            }
        }
    }
}

// ---------------- launch (R10 fork-join schedule, merged main-stream convert) ----------------
extern "C" void kernel_launch(void* const* d_in, const int* in_sizes, int n_in,
                              void* d_out, int out_size)
{
    const float* hidden = (const float*)d_in[0];
    const float* logits = (const float*)d_in[1];
    const float* w1 = (const float*)d_in[2];
    const float* w2 = (const float*)d_in[3];
    const float* w3 = (const float*)d_in[4];
    float* out = (float*)d_out;

    static int init_done = 0;
    static cudaStream_t sA, sB;
    static cudaEvent_t evRoot, evA, evB;
    if (!init_done) {
        cudaFuncSetAttribute(gemm1_mma_kernel, cudaFuncAttributeMaxDynamicSharedMemorySize, GEMM_SMEM);
        cudaFuncSetAttribute(gemm2_mma_kernel, cudaFuncAttributeMaxDynamicSharedMemorySize, GEMM_SMEM);
        cudaStreamCreateWithFlags(&sA, cudaStreamNonBlocking);
        cudaStreamCreateWithFlags(&sB, cudaStreamNonBlocking);
        cudaEventCreateWithFlags(&evRoot, cudaEventDisableTiming);
        cudaEventCreateWithFlags(&evA, cudaEventDisableTiming);
        cudaEventCreateWithFlags(&evB, cudaEventDisableTiming);
        init_done = 1;
    }

    __half *xh_p, *w1_p, *w2_p, *w3_p;
    cudaGetSymbolAddress((void**)&xh_p, g_xh);
    cudaGetSymbolAddress((void**)&w1_p, g_w1h);
    cudaGetSymbolAddress((void**)&w2_p, g_w2h);
    cudaGetSymbolAddress((void**)&w3_p, g_w3h);

    // fork
    cudaEventRecord(evRoot, 0);
    cudaStreamWaitEvent(sA, evRoot, 0);
    cudaStreamWaitEvent(sB, evRoot, 0);

    // branch A: routing chain — hidden under the main-stream converts
    zero_meta_kernel<<<1, 32, 0, sA>>>();
    route_count_kernel<<<(TT + 255) / 256, 256, 0, sA>>>(logits);
    scan_kernel<<<1, 1, 0, sA>>>();
    route_scatter_kernel<<<(TT + 255) / 256, 256, 0, sA>>>();
    cudaEventRecord(evA, sA);

    // branch B: w2 convert + out memset — hidden under GEMM1
    {
        int w4 = NE * ID * HD / 4;
        to_half_kernel<<<(w4 + 511) / 512, 256, 0, sB>>>((const float4*)w2, (uint2*)w2_p, w4);
        cudaMemsetAsync(d_out, 0, (size_t)out_size * sizeof(float), sB);
        cudaEventRecord(evB, sB);
    }

    // main stream: single merged convert for x + w1 + w3
    {
        long long total4 = (long long)NX4 + 2LL * NW4;       // 50,331,648 float4s
        long long nth = (total4 + 1) / 2;                    // 2 float4 per thread
        unsigned blocks = (unsigned)((nth + 255) / 256);
        conv3_kernel<<<blocks, 256>>>((const float4*)hidden, (uint2*)xh_p,
                                      (const float4*)w1, (uint2*)w1_p,
                                      (const float4*)w3, (uint2*)w3_p);
    }

    // join routing -> GEMM1
    cudaStreamWaitEvent(0, evA, 0);
    gemm1_mma_kernel<<<dim3(GRID_X, ID / 64, 1), 256, GEMM_SMEM>>>();

    // join w2 convert + memset -> GEMM2
    cudaStreamWaitEvent(0, evB, 0);
    gemm2_mma_kernel<<<dim3(GRID_X, HD / 128, 1), 256, GEMM_SMEM>>>(out);
}